// round 5
// baseline (speedup 1.0000x reference)
#include <cuda_runtime.h>
#include <math.h>

// Problem constants: B=128, T=128, K=8, H=3, HID=256, OUT=2
#define BT 16384   // B*T
#define TT 128
#define RPAD 260
#define TROWS 32

// Scratch (allocation-free rule: __device__ globals)
__device__ float g_Q[BT * 24];
__device__ float g_SK[BT * 24];
__device__ float g_SV[BT * 24];
__device__ float g_X32[BT * 32];

// ---------------------------------------------------------------------------
// Accurate fp32 tanh (fast-math tanhf lowers to tanh.approx.f32; keep a
// controlled-error version since outputs are ~1e-3 scale).
// ---------------------------------------------------------------------------
__device__ __forceinline__ float tanh_acc(float x) {
    float ax = fabsf(x);
    if (ax < 0.25f) {
        float x2 = x * x;
        // x * (1 - x^2/3 + 2x^4/15 - 17x^6/315)
        float p = fmaf(x2, -0.05396825396825397f, 0.13333333333333333f);
        p = fmaf(x2, p, -0.3333333333333333f);
        p = fmaf(x2, p, 1.0f);
        return x * p;
    }
    float t = __expf(2.0f * fminf(ax, 44.0f));
    float r = (t - 1.0f) / (t + 1.0f);
    return copysignf(r, x);
}

// ---------------------------------------------------------------------------
// Kernel 1: per-token projections Q = s@Wq, SK = s@Wk, SV = s@Wv  (all [BT,24])
// Also stage raw state into X32[:, 24:32].
// ---------------------------------------------------------------------------
__global__ void proj_kernel(const float* __restrict__ state,
                            const float* __restrict__ Wq,
                            const float* __restrict__ Wk,
                            const float* __restrict__ Wv) {
    __shared__ float w[576];  // Wq | Wk | Wv, each 8x24
    int tid = threadIdx.x;
    for (int i = tid; i < 192; i += 128) {
        w[i]       = Wq[i];
        w[192 + i] = Wk[i];
        w[384 + i] = Wv[i];
    }
    __syncthreads();
    int row = blockIdx.x * 128 + tid;
    float s[8];
#pragma unroll
    for (int d = 0; d < 8; d++) s[d] = state[row * 8 + d];
#pragma unroll 4
    for (int o = 0; o < 24; o++) {
        float aq = 0.f, ak = 0.f, av = 0.f;
#pragma unroll
        for (int d = 0; d < 8; d++) {
            aq = fmaf(s[d], w[d * 24 + o], aq);
            ak = fmaf(s[d], w[192 + d * 24 + o], ak);
            av = fmaf(s[d], w[384 + d * 24 + o], av);
        }
        g_Q[row * 24 + o]  = aq;
        g_SK[row * 24 + o] = ak;
        g_SV[row * 24 + o] = av;
    }
#pragma unroll
    for (int d = 0; d < 8; d++) g_X32[row * 32 + 24 + d] = s[d];
}

// ---------------------------------------------------------------------------
// Kernel 2: per (b,h) relational attention.
// scores[i,j] = q_i . SK_j / sqrt(8), softmax over j != i (the -q_i.SK_i term
// is constant per row -> cancels in softmax). x = sum_j w_j SV_j - SV_i.
// ---------------------------------------------------------------------------
__global__ void attn_kernel() {
    int b = blockIdx.x, h = blockIdx.y;
    int i = threadIdx.x;  // query row, 128 threads
    __shared__ float sk[TT][8];
    __shared__ float sv[TT][8];
    int base = (b * TT + i) * 24 + h * 8;
    float q[8];
#pragma unroll
    for (int d = 0; d < 8; d++) {
        sk[i][d] = g_SK[base + d];
        sv[i][d] = g_SV[base + d];
        q[d]     = g_Q[base + d];
    }
    __syncthreads();
    const float scale = 0.3535533905932738f;  // 1/sqrt(8)

    // pass 1: row max (excluding diagonal)
    float m = -3.0e38f;
    for (int j = 0; j < TT; j++) {
        if (j == i) continue;
        float sc = 0.f;
#pragma unroll
        for (int d = 0; d < 8; d++) sc = fmaf(q[d], sk[j][d], sc);
        sc *= scale;
        m = fmaxf(m, sc);
    }
    // pass 2: exp-sum and weighted value accumulation
    float ssum = 0.f;
    float o[8] = {0.f, 0.f, 0.f, 0.f, 0.f, 0.f, 0.f, 0.f};
    for (int j = 0; j < TT; j++) {
        if (j == i) continue;
        float sc = 0.f;
#pragma unroll
        for (int d = 0; d < 8; d++) sc = fmaf(q[d], sk[j][d], sc);
        float p = __expf(sc * scale - m);
        ssum += p;
#pragma unroll
        for (int d = 0; d < 8; d++) o[d] = fmaf(p, sv[j][d], o[d]);
    }
    float inv = 1.0f / ssum;
    int xbase = (b * TT + i) * 32 + h * 8;
#pragma unroll
    for (int d = 0; d < 8; d++) g_X32[xbase + d] = o[d] * inv - sv[i][d];
}

// ---------------------------------------------------------------------------
// Kernel 3: fused MLP + heads + rsample + log_prob for a 32-row tile.
// ---------------------------------------------------------------------------
__global__ __launch_bounds__(256) void mlp_kernel(
    const float* __restrict__ noise,
    const float* __restrict__ W1, const float* __restrict__ b1,
    const float* __restrict__ W2, const float* __restrict__ b2,
    const float* __restrict__ Wmu, const float* __restrict__ bmu,
    const float* __restrict__ Wls, const float* __restrict__ bls,
    float* __restrict__ out_action, float* __restrict__ out_logp) {
    __shared__ float xs[TROWS][36];    // padded 32->36
    __shared__ float hs[TROWS][RPAD];  // padded 256->260
    int tid  = threadIdx.x;
    int row0 = blockIdx.x * TROWS;

    // load x tile (coalesced)
    for (int i = tid; i < TROWS * 32; i += 256) {
        int r = i >> 5, c = i & 31;
        xs[r][c] = g_X32[(row0 + r) * 32 + c];
    }
    __syncthreads();

    // phase 1: h1[r][tid] for all 32 rows; W1 column in registers
    float w1c[32];
#pragma unroll
    for (int k = 0; k < 32; k++) w1c[k] = W1[k * 256 + tid];
    float bb = b1[tid];
    for (int r = 0; r < TROWS; r++) {
        float acc = bb;
#pragma unroll
        for (int k = 0; k < 32; k++) acc = fmaf(xs[r][k], w1c[k], acc);
        hs[r][tid] = fmaxf(acc, 0.0f);
    }
    __syncthreads();

    // phase 2: h2 = relu(h1 @ W2 + b2), 4 rows x 8 neurons per thread
    int lane = tid & 31, wrp = tid >> 5;
    int n0 = lane * 8, r0 = wrp * 4;
    float acc[4][8];
#pragma unroll
    for (int a = 0; a < 4; a++)
#pragma unroll
        for (int nb = 0; nb < 8; nb++) acc[a][nb] = 0.0f;

#pragma unroll 4
    for (int k = 0; k < 256; k++) {
        float4 w0 = *(const float4*)(W2 + k * 256 + n0);
        float4 w1 = *(const float4*)(W2 + k * 256 + n0 + 4);
#pragma unroll
        for (int ri = 0; ri < 4; ri++) {
            float a = hs[r0 + ri][k];  // uniform within warp -> broadcast LDS
            acc[ri][0] = fmaf(a, w0.x, acc[ri][0]);
            acc[ri][1] = fmaf(a, w0.y, acc[ri][1]);
            acc[ri][2] = fmaf(a, w0.z, acc[ri][2]);
            acc[ri][3] = fmaf(a, w0.w, acc[ri][3]);
            acc[ri][4] = fmaf(a, w1.x, acc[ri][4]);
            acc[ri][5] = fmaf(a, w1.y, acc[ri][5]);
            acc[ri][6] = fmaf(a, w1.z, acc[ri][6]);
            acc[ri][7] = fmaf(a, w1.w, acc[ri][7]);
        }
    }
    float4 bv0 = *(const float4*)(b2 + n0);
    float4 bv1 = *(const float4*)(b2 + n0 + 4);
    float bvv[8] = {bv0.x, bv0.y, bv0.z, bv0.w, bv1.x, bv1.y, bv1.z, bv1.w};
    __syncthreads();  // everyone done reading h1 before overwrite
#pragma unroll
    for (int ri = 0; ri < 4; ri++) {
        float4 s0, s1;
        s0.x = fmaxf(acc[ri][0] + bvv[0], 0.f);
        s0.y = fmaxf(acc[ri][1] + bvv[1], 0.f);
        s0.z = fmaxf(acc[ri][2] + bvv[2], 0.f);
        s0.w = fmaxf(acc[ri][3] + bvv[3], 0.f);
        s1.x = fmaxf(acc[ri][4] + bvv[4], 0.f);
        s1.y = fmaxf(acc[ri][5] + bvv[5], 0.f);
        s1.z = fmaxf(acc[ri][6] + bvv[6], 0.f);
        s1.w = fmaxf(acc[ri][7] + bvv[7], 0.f);
        *(float4*)(&hs[r0 + ri][n0])     = s0;
        *(float4*)(&hs[r0 + ri][n0 + 4]) = s1;
    }
    __syncthreads();

    // phase 3: heads + tanh-gaussian sample + log_prob (one thread per row)
    if (tid < TROWS) {
        float m0 = bmu[0], m1 = bmu[1], l0 = bls[0], l1 = bls[1];
        for (int k = 0; k < 256; k++) {
            float hv = hs[tid][k];
            m0 = fmaf(hv, Wmu[2 * k],     m0);
            m1 = fmaf(hv, Wmu[2 * k + 1], m1);
            l0 = fmaf(hv, Wls[2 * k],     l0);
            l1 = fmaf(hv, Wls[2 * k + 1], l1);
        }
        int grow = row0 + tid;
        float mu[2]  = {tanh_acc(m0), tanh_acc(m1)};
        float lsr[2] = {l0, l1};
        float lp = 0.0f;
#pragma unroll
        for (int o2 = 0; o2 < 2; o2++) {
            // log_std = MIN + 0.5*(MAX-MIN)*(tanh+1) = -20 + 11*(tanh+1)
            float ls = -20.0f + 11.0f * (tanh_acc(lsr[o2]) + 1.0f);
            float sd = __expf(ls);
            float nz = noise[grow * 2 + o2];
            float z  = mu[o2] + sd * nz;
            float a  = tanh_acc(z);
            out_action[grow * 2 + o2] = a;
            lp += (-0.5f * nz * nz - ls - 0.9189385332046727f)
                  - __logf(1.0f - a * a + 1e-7f);
        }
        out_logp[grow] = lp;
    }
}

// ---------------------------------------------------------------------------
extern "C" void kernel_launch(void* const* d_in, const int* in_sizes, int n_in,
                              void* d_out, int out_size) {
    const float* state = (const float*)d_in[0];
    const float* noise = (const float*)d_in[1];
    const float* Wq  = (const float*)d_in[2];
    const float* Wk  = (const float*)d_in[3];
    const float* Wv  = (const float*)d_in[4];
    const float* W1  = (const float*)d_in[5];
    const float* b1  = (const float*)d_in[6];
    const float* W2  = (const float*)d_in[7];
    const float* b2  = (const float*)d_in[8];
    const float* Wmu = (const float*)d_in[9];
    const float* bmu = (const float*)d_in[10];
    const float* Wls = (const float*)d_in[11];
    const float* bls = (const float*)d_in[12];
    float* out = (float*)d_out;

    proj_kernel<<<128, 128>>>(state, Wq, Wk, Wv);
    attn_kernel<<<dim3(128, 3), 128>>>();
    mlp_kernel<<<BT / TROWS, 256>>>(noise, W1, b1, W2, b2, Wmu, bmu, Wls, bls,
                                    out /*action: 32768 floats*/,
                                    out + 32768 /*log_prob: 16384 floats*/);
}

// round 8
// speedup vs baseline: 1.6704x; 1.6704x over previous
#include <cuda_runtime.h>
#include <math.h>

// Problem constants: B=128, T=128, K=8, H=3, HID=256, OUT=2
#define BT 16384
#define TT 128

// smem layout (floats), dynamic:
//  xst  [32][RP1]  at 0          : x-features transposed (k-major), 4160 floats
//  buf1 [33280]    at 4160       : union region
//     attn view : sk[3][128][8] (3072) | sv[3][128][8] (3072) | W smem (576) at +8192
//     hs_t view : [256][RPT=130]  (33280)   h1 transposed
//     hs2  view : [128][RP2=257]  (32896)   h2 row-major
#define RP1 130
#define RPT 130
#define RP2 257
#define BUF1_OFF 4160
#define SMEM_FLOATS (BUF1_OFF + 256 * RPT)      // 37440
#define SMEM_BYTES  (SMEM_FLOATS * 4)           // 149760

// ---------------------------------------------------------------------------
// f32x2 packed helpers (FFMA2 only reachable via PTX fma.rn.f32x2)
// ---------------------------------------------------------------------------
__device__ __forceinline__ unsigned long long pack2(float lo, float hi) {
    unsigned long long r;
    asm("mov.b64 %0,{%1,%2};" : "=l"(r) : "f"(lo), "f"(hi));
    return r;
}
__device__ __forceinline__ void unpack2(unsigned long long v, float& lo, float& hi) {
    asm("mov.b64 {%0,%1},%2;" : "=f"(lo), "=f"(hi) : "l"(v));
}
__device__ __forceinline__ unsigned long long ffma2(unsigned long long a,
                                                    unsigned long long b,
                                                    unsigned long long c) {
    unsigned long long d;
    asm("fma.rn.f32x2 %0,%1,%2,%3;" : "=l"(d) : "l"(a), "l"(b), "l"(c));
    return d;
}

// Accurate fp32 tanh (fast-math tanhf -> tanh.approx.f32 has ~1e-4 ABS error;
// our outputs are ~1e-3 scale, so keep a controlled-error version).
__device__ __forceinline__ float tanh_acc(float x) {
    float ax = fabsf(x);
    if (ax < 0.25f) {
        float x2 = x * x;
        float p = fmaf(x2, -0.05396825396825397f, 0.13333333333333333f);
        p = fmaf(x2, p, -0.3333333333333333f);
        p = fmaf(x2, p, 1.0f);
        return x * p;
    }
    float t = __expf(2.0f * fminf(ax, 44.0f));
    float r = (t - 1.0f) / (t + 1.0f);
    return copysignf(r, x);
}

// ---------------------------------------------------------------------------
// One block per batch b. 512 threads.
//  phase A: relational attention (threads 0..383: head h = tid>>7, query i)
//  phase 1: h1 = relu(x32 @ W1 + b1), stored transposed (FFMA2, row-paired)
//  phase 2: h2 = relu(h1 @ W2 + b2)  (FFMA2, row-paired accumulators)
//  phase 3: heads + tanh-gaussian rsample + log_prob
// ---------------------------------------------------------------------------
__global__ __launch_bounds__(512, 1) void actor_kernel(
    const float* __restrict__ state, const float* __restrict__ noise,
    const float* __restrict__ Wq, const float* __restrict__ Wk,
    const float* __restrict__ Wv,
    const float* __restrict__ W1, const float* __restrict__ b1,
    const float* __restrict__ W2, const float* __restrict__ b2,
    const float* __restrict__ Wmu, const float* __restrict__ bmu,
    const float* __restrict__ Wls, const float* __restrict__ bls,
    float* __restrict__ out_action, float* __restrict__ out_logp) {
    extern __shared__ float sm[];
    float* xst  = sm;             // [32][RP1]
    float* buf1 = sm + BUF1_OFF;

    int tid = threadIdx.x;
    int b   = blockIdx.x;

    // ---------------- phase A: attention ----------------
    float* sk = buf1;                   // [3][128][8]
    float* sv = buf1 + 3 * 128 * 8;
    float* ws = buf1 + 8192;            // Wq|Wk|Wv copies, 576 floats

    int h = tid >> 7;   // 0..3 (3 = idle in attention)
    int i = tid & 127;

    if (tid < 192) {
        ws[tid]       = Wq[tid];
        ws[192 + tid] = Wk[tid];
        ws[384 + tid] = Wv[tid];
    }
    float s[8];
    if (h < 3) {
#pragma unroll
        for (int d = 0; d < 8; d++) s[d] = state[(b * TT + i) * 8 + d];
    }
    __syncthreads();

    float q[8], vv[8];
    if (h < 3) {
        const float* wqs = ws + h * 8;
        const float* wks = ws + 192 + h * 8;
        const float* wvs = ws + 384 + h * 8;
#pragma unroll
        for (int c = 0; c < 8; c++) {
            float aq = 0.f, ak = 0.f, av = 0.f;
#pragma unroll
            for (int d = 0; d < 8; d++) {
                aq = fmaf(s[d], wqs[d * 24 + c], aq);
                ak = fmaf(s[d], wks[d * 24 + c], ak);
                av = fmaf(s[d], wvs[d * 24 + c], av);
            }
            q[c] = aq; vv[c] = av;
            sk[(h * 128 + i) * 8 + c] = ak;
            sv[(h * 128 + i) * 8 + c] = av;
        }
    }
    __syncthreads();

    if (h < 3) {
        const float scale = 0.3535533905932738f;  // 1/sqrt(8)
        const float* skh = sk + h * 1024;
        const float* svh = sv + h * 1024;
        // pass 1: row max over j != i
        float m = -3.0e38f;
        for (int j = 0; j < TT; j++) {
            if (j == i) continue;
            float sc = 0.f;
#pragma unroll
            for (int d = 0; d < 8; d++) sc = fmaf(q[d], skh[j * 8 + d], sc);
            m = fmaxf(m, sc * scale);
        }
        // pass 2: exp-sum + weighted values
        float ssum = 0.f;
        float o[8] = {0.f, 0.f, 0.f, 0.f, 0.f, 0.f, 0.f, 0.f};
        for (int j = 0; j < TT; j++) {
            if (j == i) continue;
            float sc = 0.f;
#pragma unroll
            for (int d = 0; d < 8; d++) sc = fmaf(q[d], skh[j * 8 + d], sc);
            float p = __expf(sc * scale - m);
            ssum += p;
#pragma unroll
            for (int d = 0; d < 8; d++) o[d] = fmaf(p, svh[j * 8 + d], o[d]);
        }
        float inv = 1.0f / ssum;
#pragma unroll
        for (int d = 0; d < 8; d++)
            xst[(h * 8 + d) * RP1 + i] = o[d] * inv - vv[d];
        if (h == 0) {
#pragma unroll
            for (int d = 0; d < 8; d++) xst[(24 + d) * RP1 + i] = s[d];
        }
    }
    __syncthreads();

    // ---------------- phase 1: h1 transposed ----------------
    // thread: column n = tid&255, row half = tid>>8 (64 rows as 32 pairs)
    float* hs_t = buf1;  // [256][RPT]
    {
        int n = tid & 255;
        int half = tid >> 8;
        int rbase = half * 64;
        float bb = b1[n];
        unsigned long long w1d[32];
#pragma unroll
        for (int k = 0; k < 32; k++) {
            float w = W1[k * 256 + n];
            w1d[k] = pack2(w, w);
        }
#pragma unroll 4
        for (int p = 0; p < 32; p++) {
            unsigned long long a = pack2(bb, bb);
#pragma unroll
            for (int k = 0; k < 32; k++) {
                unsigned long long x =
                    *(const unsigned long long*)(xst + k * RP1 + rbase + 2 * p);
                a = ffma2(x, w1d[k], a);
            }
            float lo, hi;
            unpack2(a, lo, hi);
            lo = fmaxf(lo, 0.f);
            hi = fmaxf(hi, 0.f);
            *(unsigned long long*)(hs_t + n * RPT + rbase + 2 * p) = pack2(lo, hi);
        }
    }
    __syncthreads();

    // ---------------- phase 2: h2 = relu(h1 @ W2 + b2) ----------------
    // warp = (rowgroup 0..3, colgroup 0..3): 32 rows x 64 cols per warp.
    // thread: 16 row-pairs x 2 cols, FFMA2 accumulators packed over rows.
    {
        int wid = tid >> 5, lane = tid & 31;
        int rbase = (wid >> 2) * 32;
        int c0 = (wid & 3) * 64 + lane * 2;

        unsigned long long acc0[16], acc1[16];
        {
            float bc0 = b2[c0], bc1 = b2[c0 + 1];
            unsigned long long B0 = pack2(bc0, bc0), B1 = pack2(bc1, bc1);
#pragma unroll
            for (int p = 0; p < 16; p++) { acc0[p] = B0; acc1[p] = B1; }
        }
#pragma unroll 2
        for (int k = 0; k < 256; k++) {
            float2 w = *(const float2*)(W2 + k * 256 + c0);
            unsigned long long Wa = pack2(w.x, w.x);
            unsigned long long Wb = pack2(w.y, w.y);
            const float* hrow = hs_t + k * RPT + rbase;
#pragma unroll
            for (int p = 0; p < 16; p++) {
                unsigned long long hx = *(const unsigned long long*)(hrow + 2 * p);
                acc0[p] = ffma2(hx, Wa, acc0[p]);
                acc1[p] = ffma2(hx, Wb, acc1[p]);
            }
        }
        __syncthreads();  // everyone done reading hs_t before overwrite
        float* hs2 = buf1;  // [128][RP2]
#pragma unroll
        for (int p = 0; p < 16; p++) {
            float l0, h0, l1, h1;
            unpack2(acc0[p], l0, h0);
            unpack2(acc1[p], l1, h1);
            int r = rbase + 2 * p;
            hs2[r * RP2 + c0]           = fmaxf(l0, 0.f);
            hs2[(r + 1) * RP2 + c0]     = fmaxf(h0, 0.f);
            hs2[r * RP2 + c0 + 1]       = fmaxf(l1, 0.f);
            hs2[(r + 1) * RP2 + c0 + 1] = fmaxf(h1, 0.f);
        }
    }
    __syncthreads();

    // ---------------- phase 3: heads + sample + log_prob ----------------
    if (tid < 128) {
        const float* hrow = buf1 + tid * RP2;
        float m0 = bmu[0], m1 = bmu[1], l0 = bls[0], l1 = bls[1];
#pragma unroll 4
        for (int k = 0; k < 256; k++) {
            float hv = hrow[k];
            float2 wm = *(const float2*)(Wmu + 2 * k);
            float2 wl = *(const float2*)(Wls + 2 * k);
            m0 = fmaf(hv, wm.x, m0);
            m1 = fmaf(hv, wm.y, m1);
            l0 = fmaf(hv, wl.x, l0);
            l1 = fmaf(hv, wl.y, l1);
        }
        int grow = b * TT + tid;
        float mu[2]  = {tanh_acc(m0), tanh_acc(m1)};
        float lsr[2] = {l0, l1};
        float lp = 0.0f;
#pragma unroll
        for (int o2 = 0; o2 < 2; o2++) {
            // log_std = -20 + 0.5*(2-(-20))*(tanh+1) = -20 + 11*(tanh+1)
            float ls = -20.0f + 11.0f * (tanh_acc(lsr[o2]) + 1.0f);
            float sd = __expf(ls);
            float nz = noise[grow * 2 + o2];
            float z  = mu[o2] + sd * nz;
            float a  = tanh_acc(z);
            out_action[grow * 2 + o2] = a;
            lp += (-0.5f * nz * nz - ls - 0.9189385332046727f)
                  - __logf(1.0f - a * a + 1e-7f);
        }
        out_logp[grow] = lp;
    }
}

// ---------------------------------------------------------------------------
extern "C" void kernel_launch(void* const* d_in, const int* in_sizes, int n_in,
                              void* d_out, int out_size) {
    const float* state = (const float*)d_in[0];
    const float* noise = (const float*)d_in[1];
    const float* Wq  = (const float*)d_in[2];
    const float* Wk  = (const float*)d_in[3];
    const float* Wv  = (const float*)d_in[4];
    const float* W1  = (const float*)d_in[5];
    const float* b1  = (const float*)d_in[6];
    const float* W2  = (const float*)d_in[7];
    const float* b2  = (const float*)d_in[8];
    const float* Wmu = (const float*)d_in[9];
    const float* bmu = (const float*)d_in[10];
    const float* Wls = (const float*)d_in[11];
    const float* bls = (const float*)d_in[12];
    float* out = (float*)d_out;

    cudaFuncSetAttribute(actor_kernel,
                         cudaFuncAttributeMaxDynamicSharedMemorySize, SMEM_BYTES);
    actor_kernel<<<128, 512, SMEM_BYTES>>>(
        state, noise, Wq, Wk, Wv, W1, b1, W2, b2, Wmu, bmu, Wls, bls,
        out /*action*/, out + 32768 /*log_prob*/);
}